// round 15
// baseline (speedup 1.0000x reference)
#include <cuda_runtime.h>
#include <cooperative_groups.h>
#include <math.h>
namespace cg = cooperative_groups;

#define LSEQ 512
#define DIM  300
#define K12  1200
#define GCL  16     // CTAs per cluster (non-portable size)
#define SL   20     // m-slice per rank (ranks 0-14; rank 15 idle on m)
#define JSL  32     // attention rows per rank
#define NT   256    // threads for xproj / pre
#define NTC  320    // threads for chain kernels + head
#define NKL  80     // 4 gates * SL outputs per rank
#define NDP  16     // d-partials for gate matvec
#define DYNA (DIM*NKL*4)                                   // 96000
#define DYNB ((DIM*NKL + JSL*DIM + JSL*DIM + DIM*SL)*4)    // 196800
#define BH_BULK (GCL*SL*4)          // 1280 B per phase barrier (16 ranks x 80B)
#define BV_BULK (GCL*24*4)          // 1536 B (16 ranks x 96B chunks)

// ---------------- device scratch ----------------
__device__ __align__(16) float g_WBT[DIM*K12];   // [d][k] recurrent weights, k=g*300+m (i,o,u,f)
__device__ __align__(16) float g_XBT[DIM*K12];   // [d][k] input weights
__device__ __align__(16) float g_W1T[DIM*DIM];   // attnh_w[k][d], d<300 -> [d][k]
__device__ __align__(16) float g_W2T[DIM*DIM];   // attnh_w[k][300+d] -> [d][k]
__device__ __align__(16) float g_X  [2*LSEQ*K12];// x projections + biases
__device__ __align__(16) float g_hsA[4*LSEQ*DIM];// phase-A hs per chain
__device__ __align__(16) float g_hmat[2*LSEQ*DIM];
__device__ __align__(16) float g_PRE[2*LSEQ*DIM];
__device__ float g_Hsum[2*DIM];
__device__ float g_bh[4*DIM];

// fast-math-immune accurate tanh
__device__ __forceinline__ float tanh_acc(float x){
    float ax = fabsf(x);
    float e = __expf(2.f*ax);
    float r = 1.f - 2.f/(e + 1.f);
    return copysignf(r, x);
}
__device__ __forceinline__ float tfast(float x){ float y; asm("tanh.approx.f32 %0,%1;" : "=f"(y) : "f"(x)); return y; }
__device__ __forceinline__ float sgm(float x){ return 1.f/(1.f+__expf(-x)); }

// ---------------- cluster bulk/mbarrier helpers ----------------
__device__ __forceinline__ uint32_t s2u(const void* p){
    return (uint32_t)__cvta_generic_to_shared((void*)p);
}
__device__ __forceinline__ uint32_t mapa_rank(uint32_t a, int r){
    uint32_t d; asm("mapa.shared::cluster.u32 %0, %1, %2;" : "=r"(d) : "r"(a), "r"(r));
    return d;
}
__device__ __forceinline__ void mbar_init(uint32_t a, uint32_t cnt){
    asm volatile("mbarrier.init.shared.b64 [%0], %1;" :: "r"(a), "r"(cnt) : "memory");
}
__device__ __forceinline__ void mbar_expect(uint32_t a, uint32_t bytes){
    asm volatile("mbarrier.arrive.expect_tx.shared.b64 _, [%0], %1;" :: "r"(a), "r"(bytes) : "memory");
}
__device__ __forceinline__ void fence_async(){
    asm volatile("fence.proxy.async.shared::cta;" ::: "memory");
}
// one bulk copy: local smem slice -> peer smem, complete_tx on peer's barrier
__device__ __forceinline__ void bulk_s2s(uint32_t dst_cluster, uint32_t src_cta,
                                         uint32_t bytes, uint32_t mbar_cluster){
    asm volatile("cp.async.bulk.shared::cluster.shared::cta.mbarrier::complete_tx::bytes "
                 "[%0], [%1], %2, [%3];"
                 :: "r"(dst_cluster), "r"(src_cta), "r"(bytes), "r"(mbar_cluster) : "memory");
}
__device__ __forceinline__ void mbar_wait(uint32_t a, int phase){
    uint32_t done;
    asm volatile("{\n\t.reg .pred p;\n\t"
        "mbarrier.try_wait.parity.acquire.cta.shared::cta.b64 p, [%1], %2;\n\t"
        "selp.b32 %0, 1, 0, p;\n\t}"
        : "=r"(done) : "r"(a), "r"((uint32_t)phase) : "memory");
    while(!done){
        asm volatile("{\n\t.reg .pred p;\n\t"
            "mbarrier.try_wait.parity.acquire.cta.shared::cta.b64 p, [%1], %2, 0x989680;\n\t"
            "selp.b32 %0, 1, 0, p;\n\t}"
            : "=r"(done) : "r"(a), "r"((uint32_t)phase) : "memory");
    }
}

// ---------------- weight transposes ----------------
__global__ void k_prep(const float* __restrict__ ioux_w, const float* __restrict__ iouh_w,
                       const float* __restrict__ fx_w,   const float* __restrict__ fh_w,
                       const float* __restrict__ attnh_w){
    int i = blockIdx.x*blockDim.x + threadIdx.x;
    if (i < DIM*K12){
        int d = i / K12, k = i % K12;
        g_WBT[i] = (k < 900) ? iouh_w[k*DIM + d] : fh_w[(k-900)*DIM + d];
        g_XBT[i] = (k < 900) ? ioux_w[k*DIM + d] : fx_w[(k-900)*DIM + d];
    }
    if (i < DIM*DIM){
        int d = i / DIM, k = i % DIM;
        g_W1T[i] = attnh_w[k*600 + d];
        g_W2T[i] = attnh_w[k*600 + 300 + d];
    }
}

// ---------------- input projections ----------------
#define TBX 8
__global__ void __launch_bounds__(NT) k_xproj(const int* __restrict__ lin, const int* __restrict__ rin,
                        const float* __restrict__ emb,
                        const float* __restrict__ ioux_b, const float* __restrict__ iouh_b,
                        const float* __restrict__ fx_b,   const float* __restrict__ fh_b){
    const int side = blockIdx.y;
    const int t0 = blockIdx.x * TBX;
    const int* idx = side ? rin : lin;
    const int tid = threadIdx.x;
    __shared__ float sx[TBX][DIM];
    for (int i = tid; i < TBX*DIM; i += NT){
        int r = i / DIM, d = i % DIM;
        sx[r][d] = emb[(long long)idx[t0+r]*DIM + d];
    }
    __syncthreads();
    float acc[5][TBX];
#pragma unroll
    for (int s = 0; s < 5; s++)
#pragma unroll
        for (int r = 0; r < TBX; r++) acc[s][r] = 0.f;
    const bool v4 = (tid < K12 - 4*NT);
    for (int d = 0; d < DIM; ++d){
        float xv[TBX];
#pragma unroll
        for (int r = 0; r < TBX; r++) xv[r] = sx[r][d];
        const float* row = g_XBT + d*K12;
#pragma unroll
        for (int s = 0; s < 4; s++){
            float w = row[tid + s*NT];
#pragma unroll
            for (int r = 0; r < TBX; r++) acc[s][r] += w*xv[r];
        }
        if (v4){
            float w = row[tid + 4*NT];
#pragma unroll
            for (int r = 0; r < TBX; r++) acc[4][r] += w*xv[r];
        }
    }
#pragma unroll
    for (int s = 0; s < 5; s++){
        int k = tid + s*NT;
        if (k < K12){
            float b = (k < 900) ? (ioux_b[k] + iouh_b[k]) : (fx_b[k-900] + fh_b[k-900]);
#pragma unroll
            for (int r = 0; r < TBX; r++)
                g_X[side*(LSEQ*K12) + (t0+r)*K12 + k] = acc[s][r] + b;
        }
    }
}

// ---- gate partials, 320 threads: 20 k-quads x 16 d-partials ----
__device__ __forceinline__ void gate_partial(const float* __restrict__ sWB,
                                             const float* __restrict__ shh,
                                             float* __restrict__ sgp /*[NDP][NKL]*/,
                                             int tid){
    int Q = tid % 20, dp = tid / 20;
    int d0 = dp*19, d1 = (dp == 15) ? DIM : d0+19;
    const float4* w4 = (const float4*)sWB;
    float4 acc = make_float4(0.f,0.f,0.f,0.f);
#pragma unroll 19
    for (int d = d0; d < d1; d++){
        float h = shh[d];
        float4 w = w4[d*20 + Q];
        acc.x += h*w.x; acc.y += h*w.y; acc.z += h*w.z; acc.w += h*w.w;
    }
    ((float4*)(sgp + dp*NKL))[Q] = acc;
}

// ---------------- phase A: 4 chains, no attention ----------------
__global__ void __cluster_dims__(GCL,1,1) __launch_bounds__(NTC,1) k_chainA(){
    extern __shared__ float dynA[];
    float* sWB = dynA;                        // [300][80]
    __shared__ __align__(16) float shhbuf[2][DIM+SL];
    __shared__ __align__(16) float sexA[2][SL];       // double-buffered push source
    __shared__ float shc[SL], sact[NKL], sgp[NDP*NKL];
    __shared__ __align__(8) unsigned long long mbA[2];
    cg::cluster_group cl = cg::this_cluster();
    const int rank = (int)cl.block_rank();
    const int chain = blockIdx.x >> 4;
    const int side = chain >> 1, rev = chain & 1;
    const int m0 = rank*SL;
    const int mcnt = (m0 < DIM) ? min(SL, DIM-m0) : 0;
    const int tid = threadIdx.x;
    for (int i = tid; i < DIM*NKL; i += NTC){
        int d = i / NKL, kl = i % NKL;
        int g = kl / 20, mm = kl % 20;
        sWB[i] = (mcnt > 0) ? g_WBT[d*K12 + g*300 + m0 + mm] : 0.f;
    }
    for (int i = tid; i < 2*(DIM+SL); i += NTC) ((float*)shhbuf)[i] = 0.f;
    if (tid < SL){ shc[tid] = 0.f; sexA[0][tid] = 0.f; sexA[1][tid] = 0.f; }
    if (tid == 0){ mbar_init(s2u(&mbA[0]), 1); mbar_init(s2u(&mbA[1]), 1); }
    __syncthreads();
    cl.sync();
    // bulk push targets: thread q (<16) sends my slice to peer q
    const int qp = (tid < GCL) ? tid : 0;
    uint32_t dA[2], mAd[2], mAl[2];
    dA[0] = mapa_rank(s2u(&shhbuf[0][m0]), qp);
    dA[1] = mapa_rank(s2u(&shhbuf[1][m0]), qp);
    mAd[0] = mapa_rank(s2u(&mbA[0]), qp);
    mAd[1] = mapa_rank(s2u(&mbA[1]), qp);
    mAl[0] = s2u(&mbA[0]); mAl[1] = s2u(&mbA[1]);
    int par[2] = {0, 0};
    for (int t = 0; t < LSEQ; t++){
        const int idx = rev ? (LSEQ-1-t) : t;
        const int rb = (t+1)&1, wb = t&1;
        const float* xrow = g_X + side*(LSEQ*K12) + idx*K12;
        if (tid == 0 && t < LSEQ-1) mbar_expect(mAl[wb], BH_BULK);
        float xv = 0.f;
        if (tid < NKL && mcnt > 0){
            int g = tid/20, mm = tid%20;
            xv = xrow[g*300 + m0 + mm];
        }
        gate_partial(sWB, shhbuf[rb], sgp, tid);
        __syncthreads();
        if (tid < NKL && mcnt > 0){
            float pre = xv;
#pragma unroll
            for (int dp = 0; dp < NDP; dp++) pre += sgp[dp*NKL + tid];
            sact[tid] = (tid/20 == 2) ? tanh_acc(pre) : sgm(pre);
        }
        __syncthreads();
        if (tid < mcnt){
            float cn = sact[tid]*sact[40+tid] + sact[60+tid]*shc[tid];
            shc[tid] = cn;
            float hp = sact[20+tid]*tanh_acc(cn);
            sexA[wb][tid] = hp;
            g_hsA[chain*(LSEQ*DIM) + t*DIM + m0 + tid] = hp;
        }
        if (t == LSEQ-1) break;
        __syncthreads();
        if (tid < GCL){ fence_async(); bulk_s2s(dA[wb], s2u(&sexA[wb][0]), SL*4, mAd[wb]); }
        mbar_wait(mAl[wb], par[wb]); par[wb] ^= 1;
    }
    cl.sync();
}

// ---------------- hmat = tanh(fwd + flipped bwd) ----------------
__global__ void k_hmat(){
    int i = blockIdx.x*blockDim.x + threadIdx.x;
    if (i >= 2*LSEQ*DIM) return;
    int s = i / (LSEQ*DIM);
    int rem = i - s*(LSEQ*DIM);
    int t = rem / DIM, m = rem % DIM;
    g_hmat[i] = tanh_acc(g_hsA[(2*s)*(LSEQ*DIM) + t*DIM + m] +
                         g_hsA[(2*s+1)*(LSEQ*DIM) + (LSEQ-1-t)*DIM + m]);
}

// ---------------- Hsum ----------------
__global__ void k_hsum(){
    int side = blockIdx.x, tid = threadIdx.x;
    if (tid >= DIM) return;
    const float* base = g_hmat + side*(LSEQ*DIM);
    float a=0,b=0,c=0,d=0;
    for (int j = 0; j < LSEQ; j += 4){
        a += base[j*DIM+tid]; b += base[(j+1)*DIM+tid];
        c += base[(j+2)*DIM+tid]; d += base[(j+3)*DIM+tid];
    }
    g_Hsum[side*DIM + tid] = (a+b)+(c+d);
}

// ---------------- PRE = hmat @ W2.T ----------------
__global__ void __launch_bounds__(NT) k_pre(){
    const int side = blockIdx.y;
    const int j00 = blockIdx.x * TBX;
    const int tid = threadIdx.x;
    __shared__ float sx[TBX][DIM];
    for (int i = tid; i < TBX*DIM; i += NT){
        int r = i / DIM, d = i % DIM;
        sx[r][d] = g_hmat[side*(LSEQ*DIM) + (j00+r)*DIM + d];
    }
    __syncthreads();
    float acc0[TBX], acc1[TBX];
#pragma unroll
    for (int r = 0; r < TBX; r++){ acc0[r]=0.f; acc1[r]=0.f; }
    const bool v1 = (tid < DIM - NT);
    for (int d = 0; d < DIM; ++d){
        float w0 = g_W2T[d*DIM + tid];
        float w1 = v1 ? g_W2T[d*DIM + tid + NT] : 0.f;
#pragma unroll
        for (int r = 0; r < TBX; r++){
            float xv = sx[r][d];
            acc0[r] += w0*xv;
            acc1[r] += w1*xv;
        }
    }
#pragma unroll
    for (int r = 0; r < TBX; r++){
        g_PRE[side*(LSEQ*DIM) + (j00+r)*DIM + tid] = acc0[r];
        if (v1) g_PRE[side*(LSEQ*DIM) + (j00+r)*DIM + tid + NT] = acc1[r];
    }
}

// ---------------- phase B: chains with attention (bulk push, 4 phases) ----------------
__global__ void __cluster_dims__(GCL,1,1) __launch_bounds__(NTC,1)
k_chainB(const float* __restrict__ Wa, const float* __restrict__ ab){
    extern __shared__ float dyn[];
    float* sWB  = dyn;                         // [300][80]
    float* sPRE = dyn + DIM*NKL;               // [32][300]
    float* sHM  = sPRE + JSL*DIM;              // [32][300]
    float* sW1  = sHM  + JSL*DIM;              // [300][20]
    __shared__ __align__(16) float shh[DIM+SL], shpre[DIM+SL], sht1[DIM+SL];
    __shared__ __align__(16) float sexh[SL], sext1[SL], sexh2[SL];
    __shared__ __align__(16) float svout[GCL*24], svin[GCL][24];
    __shared__ float shHs[DIM], shWa[DIM];
    __shared__ float shc[SL], sact[NKL], sgp[NDP*NKL], sab[SL];
    __shared__ float st1p[16][SL];
    __shared__ float shs[JSL], se[JSL], sE[1];
    __shared__ __align__(8) unsigned long long mbH[2], mbT[2], mbV[2], mbN[2];
    cg::cluster_group cl = cg::this_cluster();
    const int rank = (int)cl.block_rank();
    const int cid = blockIdx.x >> 4;
    const int side_x = (cid == 0 || cid == 2) ? 1 : 0;
    const int side_h = (cid == 0 || cid == 2) ? 0 : 1;
    const int rev = (cid >= 2);
    const int steps = (cid < 2) ? LSEQ : 1;
    const int m0 = rank*SL;
    const int mcnt = (m0 < DIM) ? min(SL, DIM-m0) : 0;
    const int j0 = rank*JSL;
    const int tid = threadIdx.x;
    // ---- one-time loads ----
    for (int i = tid; i < DIM*NKL; i += NTC){
        int d = i / NKL, kl = i % NKL;
        int g = kl / 20, mm = kl % 20;
        sWB[i] = (mcnt > 0) ? g_WBT[d*K12 + g*300 + m0 + mm] : 0.f;
    }
    for (int i = tid; i < JSL*DIM; i += NTC){
        sPRE[i] = g_PRE [side_h*(LSEQ*DIM) + j0*DIM + i];
        sHM [i] = g_hmat[side_h*(LSEQ*DIM) + j0*DIM + i];
    }
    for (int i = tid; i < DIM*SL; i += NTC){
        int d = i / SL, kl = i - d*SL;
        sW1[i] = (mcnt > 0) ? g_W1T[d*DIM + m0 + kl] : 0.f;
    }
    for (int i = tid; i < DIM+SL; i += NTC) shh[i] = 0.f;
    for (int i = tid; i < DIM; i += NTC){
        shWa[i] = Wa[i]; shHs[i] = g_Hsum[side_h*DIM + i];
    }
    if (tid < SL){ shc[tid] = 0.f; sab[tid] = (mcnt > 0) ? ab[m0+tid] : 0.f;
                   sexh[tid] = 0.f; sext1[tid] = 0.f; sexh2[tid] = 0.f; }
    if (tid == 0){
#pragma unroll
        for (int b = 0; b < 2; b++){
            mbar_init(s2u(&mbH[b]), 1); mbar_init(s2u(&mbT[b]), 1);
            mbar_init(s2u(&mbV[b]), 1); mbar_init(s2u(&mbN[b]), 1);
        }
    }
    __syncthreads();
    cl.sync();
    // ---- bulk push targets: thread q (<16) handles peer q ----
    const int qp = (tid < GCL) ? tid : 0;
    uint32_t dH = mapa_rank(s2u(&shpre[m0]), qp);
    uint32_t dT = mapa_rank(s2u(&sht1 [m0]), qp);
    uint32_t dN = mapa_rank(s2u(&shh  [m0]), qp);
    uint32_t dV = mapa_rank(s2u(&svin[rank][0]), qp);
    uint32_t srcV = s2u(&svout[qp*24]);
    uint32_t mHd[2], mTd[2], mVd[2], mNd[2];
    uint32_t lH[2], lT[2], lV[2], lN[2];
#pragma unroll
    for (int b = 0; b < 2; b++){
        mHd[b] = mapa_rank(s2u(&mbH[b]), qp);
        mTd[b] = mapa_rank(s2u(&mbT[b]), qp);
        mVd[b] = mapa_rank(s2u(&mbV[b]), qp);
        mNd[b] = mapa_rank(s2u(&mbN[b]), qp);
        lH[b] = s2u(&mbH[b]); lT[b] = s2u(&mbT[b]); lV[b] = s2u(&mbV[b]); lN[b] = s2u(&mbN[b]);
    }
    int pH[2]={0,0}, pT[2]={0,0}, pV[2]={0,0}, pN[2]={0,0};
    for (int t = 0; t < steps; t++){
        const int idx = rev ? (LSEQ-1-t) : t;
        const int b = t & 1;
        const float* xrow = g_X + side_x*(LSEQ*K12) + idx*K12;
        if (tid == 0){
            mbar_expect(lH[b], BH_BULK);
            mbar_expect(lT[b], BH_BULK);
            mbar_expect(lV[b], BV_BULK);
            if (t < steps-1) mbar_expect(lN[b], BH_BULK);
        }
        // ---- gates ----
        float xv = 0.f;
        if (tid < NKL && mcnt > 0){
            int g = tid/20, mm = tid%20;
            xv = xrow[g*300 + m0 + mm];
        }
        gate_partial(sWB, shh, sgp, tid);
        __syncthreads();
        if (tid < NKL && mcnt > 0){
            float pre = xv;
#pragma unroll
            for (int dp = 0; dp < NDP; dp++) pre += sgp[dp*NKL + tid];
            sact[tid] = (tid/20 == 2) ? tanh_acc(pre) : sgm(pre);
        }
        __syncthreads();
        if (tid < mcnt){
            float cn = sact[tid]*sact[40+tid] + sact[60+tid]*shc[tid];
            shc[tid] = cn;
            sexh[tid] = sact[20+tid]*tanh_acc(cn);
        }
        __syncthreads();
        // ---- phase H: bulk-push h_pre slice to all peers ----
        if (tid < GCL){ fence_async(); bulk_s2s(dH, s2u(&sexh[0]), SL*4, mHd[b]); }
        mbar_wait(lH[b], pH[b]); pH[b] ^= 1;
        // ---- t1 partials over full shpre ----
        {
            int kl = tid % 20, dp = tid / 20;
            int d0 = dp*19, d1 = min(DIM, d0+19);
            float a = 0.f;
            for (int d = d0; d < d1; d++) a += shpre[d]*sW1[d*SL + kl];
            st1p[dp][kl] = a;
        }
        __syncthreads();
        if (tid < SL && mcnt > 0){
            float s = sab[tid];
#pragma unroll
            for (int qq = 0; qq < 16; qq++) s += st1p[qq][tid];
            sext1[tid] = s;
        }
        __syncthreads();
        // ---- phase T: bulk-push t1 slice ----
        if (tid < GCL){ fence_async(); bulk_s2s(dT, s2u(&sext1[0]), SL*4, mTd[b]); }
        mbar_wait(lT[b], pT[b]); pT[b] ^= 1;
        // ---- scores for my 32 j rows (4 threads/row) ----
        if (tid < 4*JSL){
            int jl = tid >> 2, part = tid & 3;
            const float* pr = sPRE + jl*DIM;
            float a = 0.f;
#pragma unroll 5
            for (int i2 = 0; i2 < 75; i2++){
                int k = part + 4*i2;
                a += shWa[k]*tfast(sht1[k] + pr[k]);
            }
            a += __shfl_down_sync(0xffffffffu, a, 2);
            a += __shfl_down_sync(0xffffffffu, a, 1);
            if (part == 0) shs[jl] = a;
        }
        __syncthreads();
        if (tid < 32){
            float e = __expf(shs[tid]);
            se[tid] = e;
#pragma unroll
            for (int o = 16; o; o >>= 1) e += __shfl_xor_sync(0xffffffffu, e, o);
            if (tid == 0) sE[0] = e;
        }
        __syncthreads();
        // ---- build per-peer V chunks: [20 v | E | pad] x 16 ----
        if (tid < DIM){
            float a=0,b2=0,c=0,d=0;
#pragma unroll
            for (int j = 0; j < JSL; j += 4){
                a  += se[j  ]*sHM[(j  )*DIM + tid];
                b2 += se[j+1]*sHM[(j+1)*DIM + tid];
                c  += se[j+2]*sHM[(j+2)*DIM + tid];
                d  += se[j+3]*sHM[(j+3)*DIM + tid];
            }
            int qq = tid/20, j = tid - qq*20;
            svout[qq*24 + j] = (a+b2)+(c+d);
        } else if (tid < DIM+GCL){
            svout[(tid-DIM)*24 + 20] = sE[0];
        }
        __syncthreads();
        // ---- phase V: bulk reduce-scatter (96B chunk per peer) ----
        if (tid < GCL){ fence_async(); bulk_s2s(dV, srcV, 24*4, mVd[b]); }
        mbar_wait(lV[b], pV[b]); pV[b] ^= 1;
        // ---- hn slice ----
        if (tid < mcnt){
            float S = 0.f, vs = 0.f;
#pragma unroll
            for (int qq = 0; qq < GCL; qq++){ S += svin[qq][20]; vs += svin[qq][tid]; }
            float hn = shpre[m0+tid] + shHs[m0+tid] - vs*(1.f/S);
            if (t == steps-1) g_bh[cid*DIM + m0 + tid] = hn;
            else              sexh2[tid] = hn;
        }
        if (t == steps-1) break;
        __syncthreads();
        // ---- phase N: bulk-broadcast hn slice into shh ----
        if (tid < GCL){ fence_async(); bulk_s2s(dN, s2u(&sexh2[0]), SL*4, mNd[b]); }
        mbar_wait(lN[b], pN[b]); pN[b] ^= 1;
    }
    cl.sync();
}

// ---------------- final head ----------------
__global__ void __launch_bounds__(NTC) k_head(const float* __restrict__ wh_w, const float* __restrict__ wh_b,
                      const float* __restrict__ wp_w, const float* __restrict__ wp_b,
                      float* __restrict__ out){
    __shared__ float sv[2*600], shid[200], slog[5];
    const int tid = threadIdx.x;
    if (tid < DIM){
        float lf = tanh_acc(g_hsA[0*(LSEQ*DIM) + 511*DIM + tid] + g_bh[1*DIM + tid]);
        float lb = tanh_acc(g_hsA[1*(LSEQ*DIM) + tid]           + g_bh[3*DIM + tid]);
        float rf = tanh_acc(g_bh[0*DIM + tid] + g_hsA[2*(LSEQ*DIM) + 511*DIM + tid]);
        float rb = tanh_acc(g_bh[2*DIM + tid] + g_hsA[3*(LSEQ*DIM) + tid]);
        sv[tid]        = lf*rf;
        sv[300 + tid]  = lb*rb;
        sv[600 + tid]  = fabsf(lf - rf);
        sv[900 + tid]  = fabsf(lb - rb);
    }
    __syncthreads();
    if (tid < 200){
        const float* w = wh_w + tid*1200;
        float a=0,b=0,c=0,d=0;
        for (int e = 0; e < 1200; e += 4){
            a += sv[e]*w[e]; b += sv[e+1]*w[e+1]; c += sv[e+2]*w[e+2]; d += sv[e+3]*w[e+3];
        }
        shid[tid] = sgm((a+b)+(c+d) + wh_b[tid]);
    }
    __syncthreads();
    if (tid < 5){
        const float* w = wp_w + tid*200;
        float a=0,b=0;
        for (int h = 0; h < 200; h += 2){ a += shid[h]*w[h]; b += shid[h+1]*w[h+1]; }
        slog[tid] = a+b + wp_b[tid];
    }
    __syncthreads();
    if (tid == 0){
        float M = slog[0];
        for (int c = 1; c < 5; c++) M = fmaxf(M, slog[c]);
        float S = 0.f;
        for (int c = 0; c < 5; c++) S += expf(slog[c]-M);
        float lse = M + logf(S);
        for (int c = 0; c < 5; c++) out[c] = slog[c] - lse;
    }
}

// ---------------- launch ----------------
extern "C" void kernel_launch(void* const* d_in, const int* in_sizes, int n_in,
                              void* d_out, int out_size){
    const int*   lin     = (const int*)  d_in[0];
    const int*   rin     = (const int*)  d_in[1];
    const float* emb     = (const float*)d_in[2];
    const float* ioux_w  = (const float*)d_in[3];
    const float* ioux_b  = (const float*)d_in[4];
    const float* iouh_w  = (const float*)d_in[5];
    const float* iouh_b  = (const float*)d_in[6];
    const float* fx_w    = (const float*)d_in[7];
    const float* fx_b    = (const float*)d_in[8];
    const float* fh_w    = (const float*)d_in[9];
    const float* fh_b    = (const float*)d_in[10];
    const float* Wa      = (const float*)d_in[11];
    const float* attnh_w = (const float*)d_in[12];
    const float* attnh_b = (const float*)d_in[13];
    const float* wh_w    = (const float*)d_in[14];
    const float* wh_b    = (const float*)d_in[15];
    const float* wp_w    = (const float*)d_in[16];
    const float* wp_b    = (const float*)d_in[17];

    cudaFuncSetAttribute(k_chainA, cudaFuncAttributeNonPortableClusterSizeAllowed, 1);
    cudaFuncSetAttribute(k_chainA, cudaFuncAttributeMaxDynamicSharedMemorySize, DYNA);
    cudaFuncSetAttribute(k_chainB, cudaFuncAttributeNonPortableClusterSizeAllowed, 1);
    cudaFuncSetAttribute(k_chainB, cudaFuncAttributeMaxDynamicSharedMemorySize, DYNB);

    k_prep<<<(DIM*K12 + 255)/256, 256>>>(ioux_w, iouh_w, fx_w, fh_w, attnh_w);
    k_xproj<<<dim3(LSEQ/TBX, 2), NT>>>(lin, rin, emb, ioux_b, iouh_b, fx_b, fh_b);
    k_chainA<<<4*GCL, NTC, DYNA>>>();
    k_hmat<<<(2*LSEQ*DIM + 255)/256, 256>>>();
    k_hsum<<<2, 320>>>();
    k_pre<<<dim3(LSEQ/TBX, 2), NT>>>();
    k_chainB<<<4*GCL, NTC, DYNB>>>(Wa, attnh_b);
    k_head<<<1, NTC>>>(wh_w, wh_b, wp_w, wp_b, (float*)d_out);
}

// round 16
// speedup vs baseline: 1.1839x; 1.1839x over previous
#include <cuda_runtime.h>
#include <cooperative_groups.h>
#include <math.h>
namespace cg = cooperative_groups;

#define LSEQ 512
#define DIM  300
#define K12  1200
#define GCL  16     // CTAs per cluster (non-portable size)
#define SL   20     // m-slice per rank (ranks 0-14; rank 15 idle on m)
#define JSL  32     // attention rows per rank
#define NT   256    // threads for xproj / pre
#define NTC  320    // threads for chain kernels + head
#define NKL  80     // 4 gates * SL outputs per rank
#define GDP  4      // d-partials for gate matvec (75 d each)
#define DYNA (DIM*NKL*4)                                   // 96000
#define DYNB ((DIM*NKL + JSL*DIM + JSL*DIM + DIM*SL)*4)    // 196800

// ---------------- device scratch ----------------
__device__ __align__(16) float g_WBT[DIM*K12];   // [d][k] recurrent weights, k=g*300+m (i,o,u,f)
__device__ __align__(16) float g_XBT[DIM*K12];   // [d][k] input weights
__device__ __align__(16) float g_W1T[DIM*DIM];   // attnh_w[k][d], d<300 -> [d][k]
__device__ __align__(16) float g_W2T[DIM*DIM];   // attnh_w[k][300+d] -> [d][k]
__device__ __align__(16) float g_X  [2*LSEQ*K12];// x projections + biases
__device__ __align__(16) float g_hsA[4*LSEQ*DIM];// phase-A hs per chain
__device__ __align__(16) float g_hmat[2*LSEQ*DIM];
__device__ __align__(16) float g_PRE[2*LSEQ*DIM];
__device__ float g_Hsum[2*DIM];
__device__ float g_bh[4*DIM];

// fast-math-immune accurate tanh
__device__ __forceinline__ float tanh_acc(float x){
    float ax = fabsf(x);
    float e = __expf(2.f*ax);
    float r = 1.f - 2.f/(e + 1.f);
    return copysignf(r, x);
}
__device__ __forceinline__ float tfast(float x){ float y; asm("tanh.approx.f32 %0,%1;" : "=f"(y) : "f"(x)); return y; }
__device__ __forceinline__ float sgm(float x){ return 1.f/(1.f+__expf(-x)); }

// ---------------- cluster push/mbarrier helpers ----------------
__device__ __forceinline__ uint32_t s2u(const void* p){
    return (uint32_t)__cvta_generic_to_shared((void*)p);
}
__device__ __forceinline__ uint32_t mapa_rank(uint32_t a, int r){
    uint32_t d; asm("mapa.shared::cluster.u32 %0, %1, %2;" : "=r"(d) : "r"(a), "r"(r));
    return d;
}
__device__ __forceinline__ void mbar_init(uint32_t a, uint32_t cnt){
    asm volatile("mbarrier.init.shared.b64 [%0], %1;" :: "r"(a), "r"(cnt) : "memory");
}
__device__ __forceinline__ void mbar_expect(uint32_t a, uint32_t bytes){
    asm volatile("mbarrier.arrive.expect_tx.shared.b64 _, [%0], %1;" :: "r"(a), "r"(bytes) : "memory");
}
__device__ __forceinline__ void sta32(uint32_t ra, float v, uint32_t rb){
    asm volatile("st.async.shared::cluster.mbarrier::complete_tx::bytes.b32 [%0], %1, [%2];"
                 :: "r"(ra), "r"(__float_as_uint(v)), "r"(rb) : "memory");
}
// CTA-scope acquire wait: st.async data lands in OUR smem; barrier completion orders it.
__device__ __forceinline__ void mbar_wait(uint32_t a, int phase){
    uint32_t done;
    asm volatile("{\n\t.reg .pred p;\n\t"
        "mbarrier.try_wait.parity.acquire.cta.shared::cta.b64 p, [%1], %2;\n\t"
        "selp.b32 %0, 1, 0, p;\n\t}"
        : "=r"(done) : "r"(a), "r"((uint32_t)phase) : "memory");
    while(!done){
        asm volatile("{\n\t.reg .pred p;\n\t"
            "mbarrier.try_wait.parity.acquire.cta.shared::cta.b64 p, [%1], %2, 0x989680;\n\t"
            "selp.b32 %0, 1, 0, p;\n\t}"
            : "=r"(done) : "r"(a), "r"((uint32_t)phase) : "memory");
    }
}

// ---------------- weight transposes ----------------
__global__ void k_prep(const float* __restrict__ ioux_w, const float* __restrict__ iouh_w,
                       const float* __restrict__ fx_w,   const float* __restrict__ fh_w,
                       const float* __restrict__ attnh_w){
    int i = blockIdx.x*blockDim.x + threadIdx.x;
    if (i < DIM*K12){
        int d = i / K12, k = i % K12;
        g_WBT[i] = (k < 900) ? iouh_w[k*DIM + d] : fh_w[(k-900)*DIM + d];
        g_XBT[i] = (k < 900) ? ioux_w[k*DIM + d] : fx_w[(k-900)*DIM + d];
    }
    if (i < DIM*DIM){
        int d = i / DIM, k = i % DIM;
        g_W1T[i] = attnh_w[k*600 + d];
        g_W2T[i] = attnh_w[k*600 + 300 + d];
    }
}

// ---------------- input projections ----------------
#define TBX 8
__global__ void __launch_bounds__(NT) k_xproj(const int* __restrict__ lin, const int* __restrict__ rin,
                        const float* __restrict__ emb,
                        const float* __restrict__ ioux_b, const float* __restrict__ iouh_b,
                        const float* __restrict__ fx_b,   const float* __restrict__ fh_b){
    const int side = blockIdx.y;
    const int t0 = blockIdx.x * TBX;
    const int* idx = side ? rin : lin;
    const int tid = threadIdx.x;
    __shared__ float sx[TBX][DIM];
    for (int i = tid; i < TBX*DIM; i += NT){
        int r = i / DIM, d = i % DIM;
        sx[r][d] = emb[(long long)idx[t0+r]*DIM + d];
    }
    __syncthreads();
    float acc[5][TBX];
#pragma unroll
    for (int s = 0; s < 5; s++)
#pragma unroll
        for (int r = 0; r < TBX; r++) acc[s][r] = 0.f;
    const bool v4 = (tid < K12 - 4*NT);
    for (int d = 0; d < DIM; ++d){
        float xv[TBX];
#pragma unroll
        for (int r = 0; r < TBX; r++) xv[r] = sx[r][d];
        const float* row = g_XBT + d*K12;
#pragma unroll
        for (int s = 0; s < 4; s++){
            float w = row[tid + s*NT];
#pragma unroll
            for (int r = 0; r < TBX; r++) acc[s][r] += w*xv[r];
        }
        if (v4){
            float w = row[tid + 4*NT];
#pragma unroll
            for (int r = 0; r < TBX; r++) acc[4][r] += w*xv[r];
        }
    }
#pragma unroll
    for (int s = 0; s < 5; s++){
        int k = tid + s*NT;
        if (k < K12){
            float b = (k < 900) ? (ioux_b[k] + iouh_b[k]) : (fx_b[k-900] + fh_b[k-900]);
#pragma unroll
            for (int r = 0; r < TBX; r++)
                g_X[side*(LSEQ*K12) + (t0+r)*K12 + k] = acc[s][r] + b;
        }
    }
}

// ---- gate partials, CONFLICT-FREE: thread -> (k = tid%80, dp = tid/80), 75 d's each.
// Warp lanes read 32 consecutive floats of sWB[d][*] -> one 128B transaction, 0 conflicts.
// dp groups are 75 d apart (odd) -> straddling warps use opposite bank halves.
__device__ __forceinline__ void gate_partial(const float* __restrict__ sWB,
                                             const float* __restrict__ shh,
                                             float* __restrict__ sgp /*[GDP][NKL]*/,
                                             int tid){
    int k = tid % NKL, dp = tid / NKL;
    int d0 = dp*75;
    const float* w = sWB + k;
    float a0=0.f, a1=0.f, a2=0.f;
#pragma unroll
    for (int i = 0; i < 75; i += 3){
        a0 += shh[d0+i  ] * w[(d0+i  )*NKL];
        a1 += shh[d0+i+1] * w[(d0+i+1)*NKL];
        a2 += shh[d0+i+2] * w[(d0+i+2)*NKL];
    }
    sgp[dp*NKL + k] = (a0+a1)+a2;
}

// ---------------- phase A: 4 chains, no attention ----------------
__global__ void __cluster_dims__(GCL,1,1) __launch_bounds__(NTC,1) k_chainA(){
    extern __shared__ float dynA[];
    float* sWB = dynA;                        // [300][80]
    __shared__ float shhbuf[2][DIM+SL];
    __shared__ float shc[SL], sact[NKL], sgp[GDP*NKL], sexh[SL];
    __shared__ __align__(8) unsigned long long mbA[2];
    cg::cluster_group cl = cg::this_cluster();
    const int rank = (int)cl.block_rank();
    const int chain = blockIdx.x >> 4;
    const int side = chain >> 1, rev = chain & 1;
    const int m0 = rank*SL;
    const int mcnt = (m0 < DIM) ? min(SL, DIM-m0) : 0;
    const int tid = threadIdx.x;
    for (int i = tid; i < DIM*NKL; i += NTC){
        int d = i / NKL, kl = i % NKL;
        int g = kl / 20, mm = kl % 20;
        sWB[i] = (mcnt > 0) ? g_WBT[d*K12 + g*300 + m0 + mm] : 0.f;
    }
    for (int i = tid; i < 2*(DIM+SL); i += NTC) ((float*)shhbuf)[i] = 0.f;
    if (tid < SL) shc[tid] = 0.f;
    if (tid == 0){ mbar_init(s2u(&mbA[0]), 1); mbar_init(s2u(&mbA[1]), 1); }
    __syncthreads();
    cl.sync();
    const int q = tid / SL, lo = tid - q*SL;
    uint32_t dst[2], mbd[2], mbl[2];
    dst[0] = mapa_rank(s2u(&shhbuf[0][m0+lo]), q);
    dst[1] = mapa_rank(s2u(&shhbuf[1][m0+lo]), q);
    mbd[0] = mapa_rank(s2u(&mbA[0]), q);
    mbd[1] = mapa_rank(s2u(&mbA[1]), q);
    mbl[0] = s2u(&mbA[0]); mbl[1] = s2u(&mbA[1]);
    int par[2] = {0, 0};
    for (int t = 0; t < LSEQ; t++){
        const int idx = rev ? (LSEQ-1-t) : t;
        const int rb = (t+1)&1, wb = t&1;
        const float* xrow = g_X + side*(LSEQ*K12) + idx*K12;
        if (tid == 0 && t < LSEQ-1) mbar_expect(mbl[wb], 15*SL*4);
        float xv = 0.f;
        if (tid < NKL && mcnt > 0){
            int g = tid/20, mm = tid%20;
            xv = xrow[g*300 + m0 + mm];
        }
        gate_partial(sWB, shhbuf[rb], sgp, tid);
        __syncthreads();
        if (tid < NKL && mcnt > 0){
            float pre = xv + sgp[tid] + sgp[NKL+tid] + sgp[2*NKL+tid] + sgp[3*NKL+tid];
            sact[tid] = (tid/20 == 2) ? tanh_acc(pre) : sgm(pre);
        }
        __syncthreads();
        if (tid < mcnt){
            float cn = sact[tid]*sact[40+tid] + sact[60+tid]*shc[tid];
            shc[tid] = cn;
            float hp = sact[20+tid]*tanh_acc(cn);
            sexh[tid] = hp;
            g_hsA[chain*(LSEQ*DIM) + t*DIM + m0 + tid] = hp;
        }
        if (t == LSEQ-1) break;
        __syncthreads();
        if (mcnt > 0) sta32(dst[wb], sexh[lo], mbd[wb]);
        mbar_wait(mbl[wb], par[wb]); par[wb] ^= 1;
    }
    cl.sync();
}

// ---------------- hmat = tanh(fwd + flipped bwd) ----------------
__global__ void k_hmat(){
    int i = blockIdx.x*blockDim.x + threadIdx.x;
    if (i >= 2*LSEQ*DIM) return;
    int s = i / (LSEQ*DIM);
    int rem = i - s*(LSEQ*DIM);
    int t = rem / DIM, m = rem % DIM;
    g_hmat[i] = tanh_acc(g_hsA[(2*s)*(LSEQ*DIM) + t*DIM + m] +
                         g_hsA[(2*s+1)*(LSEQ*DIM) + (LSEQ-1-t)*DIM + m]);
}

// ---------------- Hsum ----------------
__global__ void k_hsum(){
    int side = blockIdx.x, tid = threadIdx.x;
    if (tid >= DIM) return;
    const float* base = g_hmat + side*(LSEQ*DIM);
    float a=0,b=0,c=0,d=0;
    for (int j = 0; j < LSEQ; j += 4){
        a += base[j*DIM+tid]; b += base[(j+1)*DIM+tid];
        c += base[(j+2)*DIM+tid]; d += base[(j+3)*DIM+tid];
    }
    g_Hsum[side*DIM + tid] = (a+b)+(c+d);
}

// ---------------- PRE = hmat @ W2.T ----------------
__global__ void __launch_bounds__(NT) k_pre(){
    const int side = blockIdx.y;
    const int j00 = blockIdx.x * TBX;
    const int tid = threadIdx.x;
    __shared__ float sx[TBX][DIM];
    for (int i = tid; i < TBX*DIM; i += NT){
        int r = i / DIM, d = i % DIM;
        sx[r][d] = g_hmat[side*(LSEQ*DIM) + (j00+r)*DIM + d];
    }
    __syncthreads();
    float acc0[TBX], acc1[TBX];
#pragma unroll
    for (int r = 0; r < TBX; r++){ acc0[r]=0.f; acc1[r]=0.f; }
    const bool v1 = (tid < DIM - NT);
    for (int d = 0; d < DIM; ++d){
        float w0 = g_W2T[d*DIM + tid];
        float w1 = v1 ? g_W2T[d*DIM + tid + NT] : 0.f;
#pragma unroll
        for (int r = 0; r < TBX; r++){
            float xv = sx[r][d];
            acc0[r] += w0*xv;
            acc1[r] += w1*xv;
        }
    }
#pragma unroll
    for (int r = 0; r < TBX; r++){
        g_PRE[side*(LSEQ*DIM) + (j00+r)*DIM + tid] = acc0[r];
        if (v1) g_PRE[side*(LSEQ*DIM) + (j00+r)*DIM + tid + NT] = acc1[r];
    }
}

// ---------------- phase B: chains with attention (push/mbarrier, 4 phases) ----------------
__global__ void __cluster_dims__(GCL,1,1) __launch_bounds__(NTC,1)
k_chainB(const float* __restrict__ Wa, const float* __restrict__ ab){
    extern __shared__ float dyn[];
    float* sWB  = dyn;                         // [300][80]
    float* sPRE = dyn + DIM*NKL;               // [32][300]
    float* sHM  = sPRE + JSL*DIM;              // [32][300]
    float* sW1  = sHM  + JSL*DIM;              // [300][20]
    __shared__ float shh[DIM+SL], shpre[DIM+SL], sht1[DIM+SL];
    __shared__ float shHs[DIM], shWa[DIM];
    __shared__ float shc[SL], sact[NKL], sgp[GDP*NKL], sexh[SL], sext1[SL], sexh2[SL], sab[SL];
    __shared__ float st1p[16][SL];
    __shared__ float shs[JSL], se[JSL], sE[1], sEin[GCL], svin[GCL][SL];
    __shared__ __align__(8) unsigned long long mbH[2], mbT[2], mbV[2], mbN[2];
    cg::cluster_group cl = cg::this_cluster();
    const int rank = (int)cl.block_rank();
    const int cid = blockIdx.x >> 4;
    const int side_x = (cid == 0 || cid == 2) ? 1 : 0;
    const int side_h = (cid == 0 || cid == 2) ? 0 : 1;
    const int rev = (cid >= 2);
    const int steps = (cid < 2) ? LSEQ : 1;
    const int m0 = rank*SL;
    const int mcnt = (m0 < DIM) ? min(SL, DIM-m0) : 0;
    const int j0 = rank*JSL;
    const int tid = threadIdx.x;
    // ---- one-time loads ----
    for (int i = tid; i < DIM*NKL; i += NTC){
        int d = i / NKL, kl = i % NKL;
        int g = kl / 20, mm = kl % 20;
        sWB[i] = (mcnt > 0) ? g_WBT[d*K12 + g*300 + m0 + mm] : 0.f;
    }
    for (int i = tid; i < JSL*DIM; i += NTC){
        sPRE[i] = g_PRE [side_h*(LSEQ*DIM) + j0*DIM + i];
        sHM [i] = g_hmat[side_h*(LSEQ*DIM) + j0*DIM + i];
    }
    for (int i = tid; i < DIM*SL; i += NTC){
        int d = i / SL, kl = i - d*SL;
        sW1[i] = (mcnt > 0) ? g_W1T[d*DIM + m0 + kl] : 0.f;
    }
    for (int i = tid; i < DIM+SL; i += NTC){ shh[i] = 0.f; }
    for (int i = tid; i < DIM; i += NTC){
        shWa[i] = Wa[i]; shHs[i] = g_Hsum[side_h*DIM + i];
    }
    if (tid < SL){ shc[tid] = 0.f; sab[tid] = (mcnt > 0) ? ab[m0+tid] : 0.f; }
    if (tid == 0){
#pragma unroll
        for (int b = 0; b < 2; b++){
            mbar_init(s2u(&mbH[b]), 1); mbar_init(s2u(&mbT[b]), 1);
            mbar_init(s2u(&mbV[b]), 1); mbar_init(s2u(&mbN[b]), 1);
        }
    }
    __syncthreads();
    cl.sync();
    // ---- per-thread push targets ----
    const int q = tid / SL, lo = tid - q*SL;
    uint32_t dH = mapa_rank(s2u(&shpre[m0+lo]), q);
    uint32_t dT = mapa_rank(s2u(&sht1 [m0+lo]), q);
    uint32_t dN = mapa_rank(s2u(&shh  [m0+lo]), q);
    uint32_t dV = mapa_rank(s2u(&svin[rank][lo]), q);
    const int epeer = tid - 300;
    uint32_t dE = (epeer >= 0 && epeer < GCL) ? mapa_rank(s2u(&sEin[rank]), epeer) : 0;
    uint32_t mH[2], mT[2], mV[2], mN[2], mVe[2];
    uint32_t lH[2], lT[2], lV[2], lN[2];
#pragma unroll
    for (int b = 0; b < 2; b++){
        mH[b] = mapa_rank(s2u(&mbH[b]), q);
        mT[b] = mapa_rank(s2u(&mbT[b]), q);
        mV[b] = mapa_rank(s2u(&mbV[b]), q);
        mN[b] = mapa_rank(s2u(&mbN[b]), q);
        mVe[b] = (epeer >= 0 && epeer < GCL) ? mapa_rank(s2u(&mbV[b]), epeer) : 0;
        lH[b] = s2u(&mbH[b]); lT[b] = s2u(&mbT[b]); lV[b] = s2u(&mbV[b]); lN[b] = s2u(&mbN[b]);
    }
    const uint32_t BH = 15*SL*4;
    const uint32_t BV = (mcnt > 0) ? (GCL*SL*4 + GCL*4) : (GCL*4);
    int pH[2]={0,0}, pT[2]={0,0}, pV[2]={0,0}, pN[2]={0,0};
    for (int t = 0; t < steps; t++){
        const int idx = rev ? (LSEQ-1-t) : t;
        const int b = t & 1;
        const float* xrow = g_X + side_x*(LSEQ*K12) + idx*K12;
        if (tid == 0){
            mbar_expect(lH[b], BH);
            mbar_expect(lT[b], BH);
            mbar_expect(lV[b], BV);
            if (t < steps-1) mbar_expect(lN[b], BH);
        }
        // ---- gates (SMEM weights, conflict-free) ----
        float xv = 0.f;
        if (tid < NKL && mcnt > 0){
            int g = tid/20, mm = tid%20;
            xv = xrow[g*300 + m0 + mm];
        }
        gate_partial(sWB, shh, sgp, tid);
        __syncthreads();
        if (tid < NKL && mcnt > 0){
            float pre = xv + sgp[tid] + sgp[NKL+tid] + sgp[2*NKL+tid] + sgp[3*NKL+tid];
            sact[tid] = (tid/20 == 2) ? tanh_acc(pre) : sgm(pre);
        }
        __syncthreads();
        if (tid < mcnt){
            float cn = sact[tid]*sact[40+tid] + sact[60+tid]*shc[tid];
            shc[tid] = cn;
            sexh[tid] = sact[20+tid]*tanh_acc(cn);
        }
        __syncthreads();
        // ---- phase H: push h_pre slices ----
        if (mcnt > 0) sta32(dH, sexh[lo], mH[b]);
        mbar_wait(lH[b], pH[b]); pH[b] ^= 1;
        // ---- t1 partials over full shpre ----
        {
            int kl = tid % 20, dp = tid / 20;
            int d0 = dp*19, d1 = min(DIM, d0+19);
            float a = 0.f;
            for (int d = d0; d < d1; d++) a += shpre[d]*sW1[d*SL + kl];
            st1p[dp][kl] = a;
        }
        __syncthreads();
        if (tid < SL && mcnt > 0){
            float s = sab[tid];
#pragma unroll
            for (int qq = 0; qq < 16; qq++) s += st1p[qq][tid];
            sext1[tid] = s;
        }
        __syncthreads();
        // ---- phase T: push t1 slices ----
        if (mcnt > 0) sta32(dT, sext1[lo], mT[b]);
        mbar_wait(lT[b], pT[b]); pT[b] ^= 1;
        // ---- scores for my 32 j rows (4 threads/row) ----
        if (tid < 4*JSL){
            int jl = tid >> 2, part = tid & 3;
            const float* pr = sPRE + jl*DIM;
            float a = 0.f;
#pragma unroll 5
            for (int i2 = 0; i2 < 75; i2++){
                int k = part + 4*i2;
                a += shWa[k]*tfast(sht1[k] + pr[k]);
            }
            a += __shfl_down_sync(0xffffffffu, a, 2);
            a += __shfl_down_sync(0xffffffffu, a, 1);
            if (part == 0) shs[jl] = a;
        }
        __syncthreads();
        // ---- max-free local softmax pieces ----
        if (tid < 32){
            float e = __expf(shs[tid]);
            se[tid] = e;
#pragma unroll
            for (int o = 16; o; o >>= 1) e += __shfl_xor_sync(0xffffffffu, e, o);
            if (tid == 0) sE[0] = e;
        }
        __syncthreads();
        // ---- phase V: v reduce-scatter + E broadcast ----
        if (tid < DIM){
            float a=0,b2=0,c=0,d=0;
#pragma unroll
            for (int j = 0; j < JSL; j += 4){
                a  += se[j  ]*sHM[(j  )*DIM + tid];
                b2 += se[j+1]*sHM[(j+1)*DIM + tid];
                c  += se[j+2]*sHM[(j+2)*DIM + tid];
                d  += se[j+3]*sHM[(j+3)*DIM + tid];
            }
            sta32(dV, (a+b2)+(c+d), mV[b]);
        } else if (epeer >= 0 && epeer < GCL){
            sta32(dE, sE[0], mVe[b]);
        }
        mbar_wait(lV[b], pV[b]); pV[b] ^= 1;
        // ---- hn slice ----
        if (tid < mcnt){
            float S = 0.f, vs = 0.f;
#pragma unroll
            for (int qq = 0; qq < GCL; qq++){ S += sEin[qq]; vs += svin[qq][tid]; }
            float hn = shpre[m0+tid] + shHs[m0+tid] - vs*(1.f/S);
            if (t == steps-1) g_bh[cid*DIM + m0 + tid] = hn;
            else              sexh2[tid] = hn;
        }
        if (t == steps-1) break;
        __syncthreads();
        // ---- phase N: broadcast hn slices into shh ----
        if (mcnt > 0) sta32(dN, sexh2[lo], mN[b]);
        mbar_wait(lN[b], pN[b]); pN[b] ^= 1;
    }
    cl.sync();
}

// ---------------- final head ----------------
__global__ void __launch_bounds__(NTC) k_head(const float* __restrict__ wh_w, const float* __restrict__ wh_b,
                      const float* __restrict__ wp_w, const float* __restrict__ wp_b,
                      float* __restrict__ out){
    __shared__ float sv[2*600], shid[200], slog[5];
    const int tid = threadIdx.x;
    if (tid < DIM){
        float lf = tanh_acc(g_hsA[0*(LSEQ*DIM) + 511*DIM + tid] + g_bh[1*DIM + tid]);
        float lb = tanh_acc(g_hsA[1*(LSEQ*DIM) + tid]           + g_bh[3*DIM + tid]);
        float rf = tanh_acc(g_bh[0*DIM + tid] + g_hsA[2*(LSEQ*DIM) + 511*DIM + tid]);
        float rb = tanh_acc(g_bh[2*DIM + tid] + g_hsA[3*(LSEQ*DIM) + tid]);
        sv[tid]        = lf*rf;
        sv[300 + tid]  = lb*rb;
        sv[600 + tid]  = fabsf(lf - rf);
        sv[900 + tid]  = fabsf(lb - rb);
    }
    __syncthreads();
    if (tid < 200){
        const float* w = wh_w + tid*1200;
        float a=0,b=0,c=0,d=0;
        for (int e = 0; e < 1200; e += 4){
            a += sv[e]*w[e]; b += sv[e+1]*w[e+1]; c += sv[e+2]*w[e+2]; d += sv[e+3]*w[e+3];
        }
        shid[tid] = sgm((a+b)+(c+d) + wh_b[tid]);
    }
    __syncthreads();
    if (tid < 5){
        const float* w = wp_w + tid*200;
        float a=0,b=0;
        for (int h = 0; h < 200; h += 2){ a += shid[h]*w[h]; b += shid[h+1]*w[h+1]; }
        slog[tid] = a+b + wp_b[tid];
    }
    __syncthreads();
    if (tid == 0){
        float M = slog[0];
        for (int c = 1; c < 5; c++) M = fmaxf(M, slog[c]);
        float S = 0.f;
        for (int c = 0; c < 5; c++) S += expf(slog[c]-M);
        float lse = M + logf(S);
        for (int c = 0; c < 5; c++) out[c] = slog[c] - lse;
    }
}

// ---------------- launch ----------------
extern "C" void kernel_launch(void* const* d_in, const int* in_sizes, int n_in,
                              void* d_out, int out_size){
    const int*   lin     = (const int*)  d_in[0];
    const int*   rin     = (const int*)  d_in[1];
    const float* emb     = (const float*)d_in[2];
    const float* ioux_w  = (const float*)d_in[3];
    const float* ioux_b  = (const float*)d_in[4];
    const float* iouh_w  = (const float*)d_in[5];
    const float* iouh_b  = (const float*)d_in[6];
    const float* fx_w    = (const float*)d_in[7];
    const float* fx_b    = (const float*)d_in[8];
    const float* fh_w    = (const float*)d_in[9];
    const float* fh_b    = (const float*)d_in[10];
    const float* Wa      = (const float*)d_in[11];
    const float* attnh_w = (const float*)d_in[12];
    const float* attnh_b = (const float*)d_in[13];
    const float* wh_w    = (const float*)d_in[14];
    const float* wh_b    = (const float*)d_in[15];
    const float* wp_w    = (const float*)d_in[16];
    const float* wp_b    = (const float*)d_in[17];

    cudaFuncSetAttribute(k_chainA, cudaFuncAttributeNonPortableClusterSizeAllowed, 1);
    cudaFuncSetAttribute(k_chainA, cudaFuncAttributeMaxDynamicSharedMemorySize, DYNA);
    cudaFuncSetAttribute(k_chainB, cudaFuncAttributeNonPortableClusterSizeAllowed, 1);
    cudaFuncSetAttribute(k_chainB, cudaFuncAttributeMaxDynamicSharedMemorySize, DYNB);

    k_prep<<<(DIM*K12 + 255)/256, 256>>>(ioux_w, iouh_w, fx_w, fh_w, attnh_w);
    k_xproj<<<dim3(LSEQ/TBX, 2), NT>>>(lin, rin, emb, ioux_b, iouh_b, fx_b, fh_b);
    k_chainA<<<4*GCL, NTC, DYNA>>>();
    k_hmat<<<(2*LSEQ*DIM + 255)/256, 256>>>();
    k_hsum<<<2, 320>>>();
    k_pre<<<dim3(LSEQ/TBX, 2), NT>>>();
    k_chainB<<<4*GCL, NTC, DYNB>>>(Wa, attnh_b);
    k_head<<<1, NTC>>>(wh_w, wh_b, wp_w, wp_b, (float*)d_out);
}

// round 17
// speedup vs baseline: 1.2762x; 1.0780x over previous
#include <cuda_runtime.h>
#include <cooperative_groups.h>
#include <math.h>
namespace cg = cooperative_groups;

#define LSEQ 512
#define DIM  300
#define K12  1200
#define GCL  16     // CTAs per cluster (non-portable size)
#define SL   20     // m-slice per rank (ranks 0-14; rank 15 idle on m)
#define JSL  32     // attention rows per rank
#define NT   256    // threads for xproj / pre
#define NTC  320    // threads for chain kernels + head
#define NKL  80     // 4 gates * SL outputs per rank
#define GDP  4      // d-partials for gate matvec (75 d each)
#define DYNA (DIM*NKL*4)                                   // 96000
#define DYNB ((DIM*NKL + JSL*DIM + JSL*DIM + DIM*SL)*4)    // 196800

// ---------------- device scratch ----------------
__device__ __align__(16) float g_WBT[DIM*K12];   // [d][k] recurrent weights, k=g*300+m (i,o,u,f)
__device__ __align__(16) float g_XBT[DIM*K12];   // [d][k] input weights
__device__ __align__(16) float g_W1T[DIM*DIM];   // attnh_w[k][d], d<300 -> [d][k]
__device__ __align__(16) float g_W2T[DIM*DIM];   // attnh_w[k][300+d] -> [d][k]
__device__ __align__(16) float g_X  [2*LSEQ*K12];// x projections + biases
__device__ __align__(16) float g_hsA[4*LSEQ*DIM];// phase-A hs per chain
__device__ __align__(16) float g_hmat[2*LSEQ*DIM];
__device__ __align__(16) float g_PRE[2*LSEQ*DIM];
__device__ float g_Hsum[2*DIM];
__device__ float g_bh[4*DIM];

// fast-math-immune accurate tanh
__device__ __forceinline__ float tanh_acc(float x){
    float ax = fabsf(x);
    float e = __expf(2.f*ax);
    float r = 1.f - 2.f/(e + 1.f);
    return copysignf(r, x);
}
__device__ __forceinline__ float tfast(float x){ float y; asm("tanh.approx.f32 %0,%1;" : "=f"(y) : "f"(x)); return y; }
__device__ __forceinline__ float sgm(float x){ return 1.f/(1.f+__expf(-x)); }

// ---------------- cluster push/mbarrier helpers ----------------
__device__ __forceinline__ uint32_t s2u(const void* p){
    return (uint32_t)__cvta_generic_to_shared((void*)p);
}
__device__ __forceinline__ uint32_t mapa_rank(uint32_t a, int r){
    uint32_t d; asm("mapa.shared::cluster.u32 %0, %1, %2;" : "=r"(d) : "r"(a), "r"(r));
    return d;
}
__device__ __forceinline__ void mbar_init(uint32_t a, uint32_t cnt){
    asm volatile("mbarrier.init.shared.b64 [%0], %1;" :: "r"(a), "r"(cnt) : "memory");
}
__device__ __forceinline__ void mbar_expect(uint32_t a, uint32_t bytes){
    asm volatile("mbarrier.arrive.expect_tx.shared.b64 _, [%0], %1;" :: "r"(a), "r"(bytes) : "memory");
}
__device__ __forceinline__ void sta32(uint32_t ra, float v, uint32_t rb){
    asm volatile("st.async.shared::cluster.mbarrier::complete_tx::bytes.b32 [%0], %1, [%2];"
                 :: "r"(ra), "r"(__float_as_uint(v)), "r"(rb) : "memory");
}
__device__ __forceinline__ void sta64(uint32_t ra, float x, float y, uint32_t rb){
    unsigned long long u = ((unsigned long long)__float_as_uint(y) << 32) | __float_as_uint(x);
    asm volatile("st.async.shared::cluster.mbarrier::complete_tx::bytes.b64 [%0], %1, [%2];"
                 :: "r"(ra), "l"(u), "r"(rb) : "memory");
}
// CTA-scope acquire wait — executed by ONE thread, followed by __syncthreads().
__device__ __forceinline__ void mbar_wait(uint32_t a, int phase){
    uint32_t done;
    asm volatile("{\n\t.reg .pred p;\n\t"
        "mbarrier.try_wait.parity.acquire.cta.shared::cta.b64 p, [%1], %2;\n\t"
        "selp.b32 %0, 1, 0, p;\n\t}"
        : "=r"(done) : "r"(a), "r"((uint32_t)phase) : "memory");
    while(!done){
        asm volatile("{\n\t.reg .pred p;\n\t"
            "mbarrier.try_wait.parity.acquire.cta.shared::cta.b64 p, [%1], %2, 0x989680;\n\t"
            "selp.b32 %0, 1, 0, p;\n\t}"
            : "=r"(done) : "r"(a), "r"((uint32_t)phase) : "memory");
    }
}

// ---------------- weight transposes ----------------
__global__ void k_prep(const float* __restrict__ ioux_w, const float* __restrict__ iouh_w,
                       const float* __restrict__ fx_w,   const float* __restrict__ fh_w,
                       const float* __restrict__ attnh_w){
    int i = blockIdx.x*blockDim.x + threadIdx.x;
    if (i < DIM*K12){
        int d = i / K12, k = i % K12;
        g_WBT[i] = (k < 900) ? iouh_w[k*DIM + d] : fh_w[(k-900)*DIM + d];
        g_XBT[i] = (k < 900) ? ioux_w[k*DIM + d] : fx_w[(k-900)*DIM + d];
    }
    if (i < DIM*DIM){
        int d = i / DIM, k = i % DIM;
        g_W1T[i] = attnh_w[k*600 + d];
        g_W2T[i] = attnh_w[k*600 + 300 + d];
    }
}

// ---------------- input projections ----------------
#define TBX 8
__global__ void __launch_bounds__(NT) k_xproj(const int* __restrict__ lin, const int* __restrict__ rin,
                        const float* __restrict__ emb,
                        const float* __restrict__ ioux_b, const float* __restrict__ iouh_b,
                        const float* __restrict__ fx_b,   const float* __restrict__ fh_b){
    const int side = blockIdx.y;
    const int t0 = blockIdx.x * TBX;
    const int* idx = side ? rin : lin;
    const int tid = threadIdx.x;
    __shared__ float sx[TBX][DIM];
    for (int i = tid; i < TBX*DIM; i += NT){
        int r = i / DIM, d = i % DIM;
        sx[r][d] = emb[(long long)idx[t0+r]*DIM + d];
    }
    __syncthreads();
    float acc[5][TBX];
#pragma unroll
    for (int s = 0; s < 5; s++)
#pragma unroll
        for (int r = 0; r < TBX; r++) acc[s][r] = 0.f;
    const bool v4 = (tid < K12 - 4*NT);
    for (int d = 0; d < DIM; ++d){
        float xv[TBX];
#pragma unroll
        for (int r = 0; r < TBX; r++) xv[r] = sx[r][d];
        const float* row = g_XBT + d*K12;
#pragma unroll
        for (int s = 0; s < 4; s++){
            float w = row[tid + s*NT];
#pragma unroll
            for (int r = 0; r < TBX; r++) acc[s][r] += w*xv[r];
        }
        if (v4){
            float w = row[tid + 4*NT];
#pragma unroll
            for (int r = 0; r < TBX; r++) acc[4][r] += w*xv[r];
        }
    }
#pragma unroll
    for (int s = 0; s < 5; s++){
        int k = tid + s*NT;
        if (k < K12){
            float b = (k < 900) ? (ioux_b[k] + iouh_b[k]) : (fx_b[k-900] + fh_b[k-900]);
#pragma unroll
            for (int r = 0; r < TBX; r++)
                g_X[side*(LSEQ*K12) + (t0+r)*K12 + k] = acc[s][r] + b;
        }
    }
}

// ---- gate partials, conflict-free: thread -> (k = tid%80, dp = tid/80), 75 d's each ----
__device__ __forceinline__ void gate_partial(const float* __restrict__ sWB,
                                             const float* __restrict__ shh,
                                             float* __restrict__ sgp /*[GDP][NKL]*/,
                                             int tid){
    int k = tid % NKL, dp = tid / NKL;
    int d0 = dp*75;
    const float* w = sWB + k;
    float a0=0.f, a1=0.f, a2=0.f;
#pragma unroll
    for (int i = 0; i < 75; i += 3){
        a0 += shh[d0+i  ] * w[(d0+i  )*NKL];
        a1 += shh[d0+i+1] * w[(d0+i+1)*NKL];
        a2 += shh[d0+i+2] * w[(d0+i+2)*NKL];
    }
    sgp[dp*NKL + k] = (a0+a1)+a2;
}

// ---------------- phase A: 4 chains, no attention ----------------
__global__ void __cluster_dims__(GCL,1,1) __launch_bounds__(NTC,1) k_chainA(){
    extern __shared__ float dynA[];
    float* sWB = dynA;                        // [300][80]
    __shared__ __align__(16) float shhbuf[2][DIM+SL];
    __shared__ __align__(16) float sexh[SL];
    __shared__ float shc[SL], sact[NKL], sgp[GDP*NKL];
    __shared__ __align__(8) unsigned long long mbA[2];
    cg::cluster_group cl = cg::this_cluster();
    const int rank = (int)cl.block_rank();
    const int chain = blockIdx.x >> 4;
    const int side = chain >> 1, rev = chain & 1;
    const int m0 = rank*SL;
    const int mcnt = (m0 < DIM) ? min(SL, DIM-m0) : 0;
    const int tid = threadIdx.x;
    for (int i = tid; i < DIM*NKL; i += NTC){
        int d = i / NKL, kl = i % NKL;
        int g = kl / 20, mm = kl % 20;
        sWB[i] = (mcnt > 0) ? g_WBT[d*K12 + g*300 + m0 + mm] : 0.f;
    }
    for (int i = tid; i < 2*(DIM+SL); i += NTC) ((float*)shhbuf)[i] = 0.f;
    if (tid < SL) shc[tid] = 0.f;
    if (tid == 0){ mbar_init(s2u(&mbA[0]), 1); mbar_init(s2u(&mbA[1]), 1); }
    __syncthreads();
    cl.sync();
    // b64 push mapping: tid<160 -> peer q = tid/10, pair offset lo = (tid%10)*2
    const int q = tid / 10, lo = (tid % 10) * 2;
    uint32_t dst[2], mbd[2], mbl[2];
    dst[0] = mapa_rank(s2u(&shhbuf[0][m0+lo]), q);
    dst[1] = mapa_rank(s2u(&shhbuf[1][m0+lo]), q);
    mbd[0] = mapa_rank(s2u(&mbA[0]), q);
    mbd[1] = mapa_rank(s2u(&mbA[1]), q);
    mbl[0] = s2u(&mbA[0]); mbl[1] = s2u(&mbA[1]);
    int par[2] = {0, 0};
    for (int t = 0; t < LSEQ; t++){
        const int idx = rev ? (LSEQ-1-t) : t;
        const int rb = (t+1)&1, wb = t&1;
        const float* xrow = g_X + side*(LSEQ*K12) + idx*K12;
        if (tid == 0 && t < LSEQ-1) mbar_expect(mbl[wb], 15*SL*4);
        float xv = 0.f;
        if (tid < NKL && mcnt > 0){
            int g = tid/20, mm = tid%20;
            xv = xrow[g*300 + m0 + mm];
        }
        gate_partial(sWB, shhbuf[rb], sgp, tid);
        __syncthreads();
        if (tid < NKL && mcnt > 0){
            float pre = xv + sgp[tid] + sgp[NKL+tid] + sgp[2*NKL+tid] + sgp[3*NKL+tid];
            sact[tid] = (tid/20 == 2) ? tanh_acc(pre) : sgm(pre);
        }
        __syncthreads();
        if (tid < mcnt){
            float cn = sact[tid]*sact[40+tid] + sact[60+tid]*shc[tid];
            shc[tid] = cn;
            float hp = sact[20+tid]*tanh_acc(cn);
            sexh[tid] = hp;
            g_hsA[chain*(LSEQ*DIM) + t*DIM + m0 + tid] = hp;
        }
        if (t == LSEQ-1) break;
        __syncthreads();
        if (tid < 160 && mcnt > 0) sta64(dst[wb], sexh[lo], sexh[lo+1], mbd[wb]);
        if (tid == 0) mbar_wait(mbl[wb], par[wb]);
        par[wb] ^= 1;
        __syncthreads();
    }
    cl.sync();
}

// ---------------- hmat = tanh(fwd + flipped bwd) ----------------
__global__ void k_hmat(){
    int i = blockIdx.x*blockDim.x + threadIdx.x;
    if (i >= 2*LSEQ*DIM) return;
    int s = i / (LSEQ*DIM);
    int rem = i - s*(LSEQ*DIM);
    int t = rem / DIM, m = rem % DIM;
    g_hmat[i] = tanh_acc(g_hsA[(2*s)*(LSEQ*DIM) + t*DIM + m] +
                         g_hsA[(2*s+1)*(LSEQ*DIM) + (LSEQ-1-t)*DIM + m]);
}

// ---------------- Hsum ----------------
__global__ void k_hsum(){
    int side = blockIdx.x, tid = threadIdx.x;
    if (tid >= DIM) return;
    const float* base = g_hmat + side*(LSEQ*DIM);
    float a=0,b=0,c=0,d=0;
    for (int j = 0; j < LSEQ; j += 4){
        a += base[j*DIM+tid]; b += base[(j+1)*DIM+tid];
        c += base[(j+2)*DIM+tid]; d += base[(j+3)*DIM+tid];
    }
    g_Hsum[side*DIM + tid] = (a+b)+(c+d);
}

// ---------------- PRE = hmat @ W2.T ----------------
__global__ void __launch_bounds__(NT) k_pre(){
    const int side = blockIdx.y;
    const int j00 = blockIdx.x * TBX;
    const int tid = threadIdx.x;
    __shared__ float sx[TBX][DIM];
    for (int i = tid; i < TBX*DIM; i += NT){
        int r = i / DIM, d = i % DIM;
        sx[r][d] = g_hmat[side*(LSEQ*DIM) + (j00+r)*DIM + d];
    }
    __syncthreads();
    float acc0[TBX], acc1[TBX];
#pragma unroll
    for (int r = 0; r < TBX; r++){ acc0[r]=0.f; acc1[r]=0.f; }
    const bool v1 = (tid < DIM - NT);
    for (int d = 0; d < DIM; ++d){
        float w0 = g_W2T[d*DIM + tid];
        float w1 = v1 ? g_W2T[d*DIM + tid + NT] : 0.f;
#pragma unroll
        for (int r = 0; r < TBX; r++){
            float xv = sx[r][d];
            acc0[r] += w0*xv;
            acc1[r] += w1*xv;
        }
    }
#pragma unroll
    for (int r = 0; r < TBX; r++){
        g_PRE[side*(LSEQ*DIM) + (j00+r)*DIM + tid] = acc0[r];
        if (v1) g_PRE[side*(LSEQ*DIM) + (j00+r)*DIM + tid + NT] = acc1[r];
    }
}

// ---------------- phase B: chains with attention (b64 push, single-thread wait) ----------------
__global__ void __cluster_dims__(GCL,1,1) __launch_bounds__(NTC,1)
k_chainB(const float* __restrict__ Wa, const float* __restrict__ ab){
    extern __shared__ float dyn[];
    float* sWB  = dyn;                         // [300][80]
    float* sPRE = dyn + DIM*NKL;               // [32][300]
    float* sHM  = sPRE + JSL*DIM;              // [32][300]
    float* sW1  = sHM  + JSL*DIM;              // [300][20]
    __shared__ __align__(16) float shh[DIM+SL], shpre[DIM+SL], sht1[DIM+SL];
    __shared__ __align__(16) float sexh[SL], sext1[SL], sexh2[SL];
    __shared__ __align__(16) float svin[GCL][SL];
    __shared__ float shHs[DIM], shWa[DIM];
    __shared__ float shc[SL], sact[NKL], sgp[GDP*NKL], sab[SL];
    __shared__ float st1p[16][SL];
    __shared__ float shs[JSL], se[JSL], sE[1], sEin[GCL];
    __shared__ __align__(8) unsigned long long mbH[2], mbT[2], mbV[2], mbN[2];
    cg::cluster_group cl = cg::this_cluster();
    const int rank = (int)cl.block_rank();
    const int cid = blockIdx.x >> 4;
    const int side_x = (cid == 0 || cid == 2) ? 1 : 0;
    const int side_h = (cid == 0 || cid == 2) ? 0 : 1;
    const int rev = (cid >= 2);
    const int steps = (cid < 2) ? LSEQ : 1;
    const int m0 = rank*SL;
    const int mcnt = (m0 < DIM) ? min(SL, DIM-m0) : 0;
    const int j0 = rank*JSL;
    const int tid = threadIdx.x;
    // ---- one-time loads ----
    for (int i = tid; i < DIM*NKL; i += NTC){
        int d = i / NKL, kl = i % NKL;
        int g = kl / 20, mm = kl % 20;
        sWB[i] = (mcnt > 0) ? g_WBT[d*K12 + g*300 + m0 + mm] : 0.f;
    }
    for (int i = tid; i < JSL*DIM; i += NTC){
        sPRE[i] = g_PRE [side_h*(LSEQ*DIM) + j0*DIM + i];
        sHM [i] = g_hmat[side_h*(LSEQ*DIM) + j0*DIM + i];
    }
    for (int i = tid; i < DIM*SL; i += NTC){
        int d = i / SL, kl = i - d*SL;
        sW1[i] = (mcnt > 0) ? g_W1T[d*DIM + m0 + kl] : 0.f;
    }
    for (int i = tid; i < DIM+SL; i += NTC){ shh[i] = 0.f; }
    for (int i = tid; i < DIM; i += NTC){
        shWa[i] = Wa[i]; shHs[i] = g_Hsum[side_h*DIM + i];
    }
    if (tid < SL){ shc[tid] = 0.f; sab[tid] = (mcnt > 0) ? ab[m0+tid] : 0.f; }
    if (tid == 0){
#pragma unroll
        for (int b = 0; b < 2; b++){
            mbar_init(s2u(&mbH[b]), 1); mbar_init(s2u(&mbT[b]), 1);
            mbar_init(s2u(&mbV[b]), 1); mbar_init(s2u(&mbN[b]), 1);
        }
    }
    __syncthreads();
    cl.sync();
    // ---- per-thread push targets ----
    // Slice pushes (H/T/N): tid<160 -> peer q = tid/10, pair lo = (tid%10)*2
    const int q = tid / 10, lo = (tid % 10) * 2;
    uint32_t dH = mapa_rank(s2u(&shpre[m0+lo]), q);
    uint32_t dT = mapa_rank(s2u(&sht1 [m0+lo]), q);
    uint32_t dN = mapa_rank(s2u(&shh  [m0+lo]), q);
    // V pushes: tid<150 -> peer qv = tid/10, pair j2 = (tid%10)*2, elements m = qv*20+j2,+1
    const int qv = (tid < 150) ? tid/10 : 0;
    const int j2 = (tid % 10) * 2;
    uint32_t dV = mapa_rank(s2u(&svin[rank][j2]), qv);
    const int epeer = tid - 300;
    uint32_t dE = (epeer >= 0 && epeer < GCL) ? mapa_rank(s2u(&sEin[rank]), epeer) : 0;
    uint32_t mH[2], mT[2], mV[2], mN[2], mVv[2], mVe[2];
    uint32_t lH[2], lT[2], lV[2], lN[2];
#pragma unroll
    for (int b = 0; b < 2; b++){
        mH[b] = mapa_rank(s2u(&mbH[b]), q);
        mT[b] = mapa_rank(s2u(&mbT[b]), q);
        mN[b] = mapa_rank(s2u(&mbN[b]), q);
        mVv[b] = mapa_rank(s2u(&mbV[b]), qv);
        mVe[b] = (epeer >= 0 && epeer < GCL) ? mapa_rank(s2u(&mbV[b]), epeer) : 0;
        mV[b] = mVv[b];
        lH[b] = s2u(&mbH[b]); lT[b] = s2u(&mbT[b]); lV[b] = s2u(&mbV[b]); lN[b] = s2u(&mbN[b]);
    }
    const uint32_t BH = 15*SL*4;
    const uint32_t BV = (mcnt > 0) ? (GCL*SL*4 + GCL*4) : (GCL*4);
    int pH[2]={0,0}, pT[2]={0,0}, pV[2]={0,0}, pN[2]={0,0};
    for (int t = 0; t < steps; t++){
        const int idx = rev ? (LSEQ-1-t) : t;
        const int b = t & 1;
        const float* xrow = g_X + side_x*(LSEQ*K12) + idx*K12;
        if (tid == 0){
            mbar_expect(lH[b], BH);
            mbar_expect(lT[b], BH);
            mbar_expect(lV[b], BV);
            if (t < steps-1) mbar_expect(lN[b], BH);
        }
        // ---- gates (SMEM weights, conflict-free) ----
        float xv = 0.f;
        if (tid < NKL && mcnt > 0){
            int g = tid/20, mm = tid%20;
            xv = xrow[g*300 + m0 + mm];
        }
        gate_partial(sWB, shh, sgp, tid);
        __syncthreads();
        if (tid < NKL && mcnt > 0){
            float pre = xv + sgp[tid] + sgp[NKL+tid] + sgp[2*NKL+tid] + sgp[3*NKL+tid];
            sact[tid] = (tid/20 == 2) ? tanh_acc(pre) : sgm(pre);
        }
        __syncthreads();
        if (tid < mcnt){
            float cn = sact[tid]*sact[40+tid] + sact[60+tid]*shc[tid];
            shc[tid] = cn;
            sexh[tid] = sact[20+tid]*tanh_acc(cn);
        }
        __syncthreads();
        // ---- phase H: push h_pre slices (b64) ----
        if (tid < 160 && mcnt > 0) sta64(dH, sexh[lo], sexh[lo+1], mH[b]);
        if (tid == 0) mbar_wait(lH[b], pH[b]);
        pH[b] ^= 1;
        __syncthreads();
        // ---- t1 partials over full shpre ----
        {
            int kl = tid % 20, dp = tid / 20;
            int d0 = dp*19, d1 = min(DIM, d0+19);
            float a = 0.f;
            for (int d = d0; d < d1; d++) a += shpre[d]*sW1[d*SL + kl];
            st1p[dp][kl] = a;
        }
        __syncthreads();
        if (tid < SL && mcnt > 0){
            float s = sab[tid];
#pragma unroll
            for (int qq = 0; qq < 16; qq++) s += st1p[qq][tid];
            sext1[tid] = s;
        }
        __syncthreads();
        // ---- phase T: push t1 slices (b64) ----
        if (tid < 160 && mcnt > 0) sta64(dT, sext1[lo], sext1[lo+1], mT[b]);
        if (tid == 0) mbar_wait(lT[b], pT[b]);
        pT[b] ^= 1;
        __syncthreads();
        // ---- scores for my 32 j rows (4 threads/row) ----
        if (tid < 4*JSL){
            int jl = tid >> 2, part = tid & 3;
            const float* pr = sPRE + jl*DIM;
            float a = 0.f;
#pragma unroll 5
            for (int i2 = 0; i2 < 75; i2++){
                int k = part + 4*i2;
                a += shWa[k]*tfast(sht1[k] + pr[k]);
            }
            a += __shfl_down_sync(0xffffffffu, a, 2);
            a += __shfl_down_sync(0xffffffffu, a, 1);
            if (part == 0) shs[jl] = a;
        }
        __syncthreads();
        // ---- max-free local softmax pieces ----
        if (tid < 32){
            float e = __expf(shs[tid]);
            se[tid] = e;
#pragma unroll
            for (int o = 16; o; o >>= 1) e += __shfl_xor_sync(0xffffffffu, e, o);
            if (tid == 0) sE[0] = e;
        }
        __syncthreads();
        // ---- phase V: v reduce-scatter (b64 pairs) + E broadcast ----
        if (tid < 150){
            int m = qv*20 + j2;
            float a0=0,b0=0,a1=0,b1=0;
#pragma unroll
            for (int j = 0; j < JSL; j += 2){
                float s0 = se[j], s1 = se[j+1];
                a0 += s0*sHM[(j  )*DIM + m];   b0 += s1*sHM[(j+1)*DIM + m];
                a1 += s0*sHM[(j  )*DIM + m+1]; b1 += s1*sHM[(j+1)*DIM + m+1];
            }
            sta64(dV, a0+b0, a1+b1, mVv[b]);
        } else if (epeer >= 0 && epeer < GCL){
            sta32(dE, sE[0], mVe[b]);
        }
        if (tid == 0) mbar_wait(lV[b], pV[b]);
        pV[b] ^= 1;
        __syncthreads();
        // ---- hn slice ----
        if (tid < mcnt){
            float S = 0.f, vs = 0.f;
#pragma unroll
            for (int qq = 0; qq < GCL; qq++){ S += sEin[qq]; vs += svin[qq][tid]; }
            float hn = shpre[m0+tid] + shHs[m0+tid] - vs*(1.f/S);
            if (t == steps-1) g_bh[cid*DIM + m0 + tid] = hn;
            else              sexh2[tid] = hn;
        }
        if (t == steps-1) break;
        __syncthreads();
        // ---- phase N: broadcast hn slices (b64) ----
        if (tid < 160 && mcnt > 0) sta64(dN, sexh2[lo], sexh2[lo+1], mN[b]);
        if (tid == 0) mbar_wait(lN[b], pN[b]);
        pN[b] ^= 1;
        __syncthreads();
    }
    cl.sync();
}

// ---------------- final head ----------------
__global__ void __launch_bounds__(NTC) k_head(const float* __restrict__ wh_w, const float* __restrict__ wh_b,
                      const float* __restrict__ wp_w, const float* __restrict__ wp_b,
                      float* __restrict__ out){
    __shared__ float sv[2*600], shid[200], slog[5];
    const int tid = threadIdx.x;
    if (tid < DIM){
        float lf = tanh_acc(g_hsA[0*(LSEQ*DIM) + 511*DIM + tid] + g_bh[1*DIM + tid]);
        float lb = tanh_acc(g_hsA[1*(LSEQ*DIM) + tid]           + g_bh[3*DIM + tid]);
        float rf = tanh_acc(g_bh[0*DIM + tid] + g_hsA[2*(LSEQ*DIM) + 511*DIM + tid]);
        float rb = tanh_acc(g_bh[2*DIM + tid] + g_hsA[3*(LSEQ*DIM) + tid]);
        sv[tid]        = lf*rf;
        sv[300 + tid]  = lb*rb;
        sv[600 + tid]  = fabsf(lf - rf);
        sv[900 + tid]  = fabsf(lb - rb);
    }
    __syncthreads();
    if (tid < 200){
        const float* w = wh_w + tid*1200;
        float a=0,b=0,c=0,d=0;
        for (int e = 0; e < 1200; e += 4){
            a += sv[e]*w[e]; b += sv[e+1]*w[e+1]; c += sv[e+2]*w[e+2]; d += sv[e+3]*w[e+3];
        }
        shid[tid] = sgm((a+b)+(c+d) + wh_b[tid]);
    }
    __syncthreads();
    if (tid < 5){
        const float* w = wp_w + tid*200;
        float a=0,b=0;
        for (int h = 0; h < 200; h += 2){ a += shid[h]*w[h]; b += shid[h+1]*w[h+1]; }
        slog[tid] = a+b + wp_b[tid];
    }
    __syncthreads();
    if (tid == 0){
        float M = slog[0];
        for (int c = 1; c < 5; c++) M = fmaxf(M, slog[c]);
        float S = 0.f;
        for (int c = 0; c < 5; c++) S += expf(slog[c]-M);
        float lse = M + logf(S);
        for (int c = 0; c < 5; c++) out[c] = slog[c] - lse;
    }
}

// ---------------- launch ----------------
extern "C" void kernel_launch(void* const* d_in, const int* in_sizes, int n_in,
                              void* d_out, int out_size){
    const int*   lin     = (const int*)  d_in[0];
    const int*   rin     = (const int*)  d_in[1];
    const float* emb     = (const float*)d_in[2];
    const float* ioux_w  = (const float*)d_in[3];
    const float* ioux_b  = (const float*)d_in[4];
    const float* iouh_w  = (const float*)d_in[5];
    const float* iouh_b  = (const float*)d_in[6];
    const float* fx_w    = (const float*)d_in[7];
    const float* fx_b    = (const float*)d_in[8];
    const float* fh_w    = (const float*)d_in[9];
    const float* fh_b    = (const float*)d_in[10];
    const float* Wa      = (const float*)d_in[11];
    const float* attnh_w = (const float*)d_in[12];
    const float* attnh_b = (const float*)d_in[13];
    const float* wh_w    = (const float*)d_in[14];
    const float* wh_b    = (const float*)d_in[15];
    const float* wp_w    = (const float*)d_in[16];
    const float* wp_b    = (const float*)d_in[17];

    cudaFuncSetAttribute(k_chainA, cudaFuncAttributeNonPortableClusterSizeAllowed, 1);
    cudaFuncSetAttribute(k_chainA, cudaFuncAttributeMaxDynamicSharedMemorySize, DYNA);
    cudaFuncSetAttribute(k_chainB, cudaFuncAttributeNonPortableClusterSizeAllowed, 1);
    cudaFuncSetAttribute(k_chainB, cudaFuncAttributeMaxDynamicSharedMemorySize, DYNB);

    k_prep<<<(DIM*K12 + 255)/256, 256>>>(ioux_w, iouh_w, fx_w, fh_w, attnh_w);
    k_xproj<<<dim3(LSEQ/TBX, 2), NT>>>(lin, rin, emb, ioux_b, iouh_b, fx_b, fh_b);
    k_chainA<<<4*GCL, NTC, DYNA>>>();
    k_hmat<<<(2*LSEQ*DIM + 255)/256, 256>>>();
    k_hsum<<<2, 320>>>();
    k_pre<<<dim3(LSEQ/TBX, 2), NT>>>();
    k_chainB<<<4*GCL, NTC, DYNB>>>(Wa, attnh_b);
    k_head<<<1, NTC>>>(wh_w, wh_b, wp_w, wp_b, (float*)d_out);
}